// round 3
// baseline (speedup 1.0000x reference)
#include <cuda_runtime.h>
#include <math.h>

// Problem constants
#define BB   32
#define NN_  577
#define CC   768
#define HH_  12
#define DD   64
#define HID_ 3072
#define ROWS (BB*NN_)            // 18464
#define SMAT ((long long)NN_*NN_)  // 332929 per (b,h)
#define ALPHA_ 0.1f
#define EPS_ 1e-6f
#define SCALE_ 0.125f            // D^-0.5

// ---------------- scratch (static device arrays; no allocations allowed) ---
__device__ float g_hln [ (long long)ROWS*CC ];      // LN1 output
__device__ float g_qkv [ (long long)ROWS*3*CC ];    // qkv, [row, 3*C]
__device__ float g_scores[ (long long)BB*HH_*SMAT ];// attention scores
__device__ float g_attnout[ (long long)ROWS*CC ];   // attn output in [B,N,C]
__device__ float g_x1  [ (long long)ROWS*CC ];      // x + proj
__device__ float g_h2ln[ (long long)ROWS*CC ];      // LN2 output
__device__ float g_fc1 [ (long long)ROWS*HID_ ];    // gelu(fc1)

// ---------------- generic tiled GEMM ---------------------------------------
// C[M,N] = epi( alpha * A[M,K] @ op(B) + bias ),  op(B)=B^T if BT (B is [N,K])
// Batched via blockIdx.z with composite offsets: z -> (z/HB)*s?o + (z%HB)*s?i
// EPI: 0 = none, 1 = exact GELU, 2 = add residual Res[r*ldRes + c]
template<int BM,int BN,int BK,int TM,int TN,bool BT,int EPI>
__global__ void gemm_k(const float* __restrict__ A, const float* __restrict__ Bm,
                       float* __restrict__ C,
                       int M, int N, int K,
                       int ldA, int ldB, int ldC,
                       int HB,
                       long long sAo, long long sAi,
                       long long sBo, long long sBi,
                       long long sCo, long long sCi,
                       const float* __restrict__ bias,
                       const float* __restrict__ Res, int ldRes,
                       float alpha)
{
    constexpr int THREADS = (BM/TM)*(BN/TN);
    int z = blockIdx.z;
    int zo = z / HB, zi = z % HB;
    A  += zo*sAo + zi*sAi;
    Bm += zo*sBo + zi*sBi;
    C  += zo*sCo + zi*sCi;

    __shared__ float As[BK][BM];
    __shared__ float Bs[BK][BN];

    const int tx = threadIdx.x;          // BN/TN wide
    const int ty = threadIdx.y;          // BM/TM tall
    const int t  = ty*blockDim.x + tx;
    const int rowBase = blockIdx.y * BM;
    const int colBase = blockIdx.x * BN;

    float acc[TM][TN];
#pragma unroll
    for (int i = 0; i < TM; i++)
#pragma unroll
        for (int j = 0; j < TN; j++) acc[i][j] = 0.f;

    for (int k0 = 0; k0 < K; k0 += BK) {
        // load A tile (BM x BK) -> As[k][m]
#pragma unroll
        for (int e = t; e < BM*BK; e += THREADS) {
            int r = e / BK, k = e % BK;
            int gr = rowBase + r, gk = k0 + k;
            As[k][r] = (gr < M && gk < K) ? A[(long long)gr*ldA + gk] : 0.f;
        }
        if (BT) {
            // B is [N,K]; tile BN x BK -> Bs[k][n]
#pragma unroll
            for (int e = t; e < BN*BK; e += THREADS) {
                int n = e / BK, k = e % BK;
                int gn = colBase + n, gk = k0 + k;
                Bs[k][n] = (gn < N && gk < K) ? Bm[(long long)gn*ldB + gk] : 0.f;
            }
        } else {
            // B is [K,N]; tile BK x BN -> Bs[k][n]
#pragma unroll
            for (int e = t; e < BK*BN; e += THREADS) {
                int k = e / BN, n = e % BN;
                int gk = k0 + k, gn = colBase + n;
                Bs[k][n] = (gn < N && gk < K) ? Bm[(long long)gk*ldB + gn] : 0.f;
            }
        }
        __syncthreads();

#pragma unroll
        for (int kk = 0; kk < BK; kk++) {
            float a[TM], b[TN];
#pragma unroll
            for (int i = 0; i < TM; i += 4) {
                float4 v = *reinterpret_cast<const float4*>(&As[kk][ty*TM + i]);
                a[i] = v.x; a[i+1] = v.y; a[i+2] = v.z; a[i+3] = v.w;
            }
#pragma unroll
            for (int j = 0; j < TN; j += 4) {
                float4 v = *reinterpret_cast<const float4*>(&Bs[kk][tx*TN + j]);
                b[j] = v.x; b[j+1] = v.y; b[j+2] = v.z; b[j+3] = v.w;
            }
#pragma unroll
            for (int i = 0; i < TM; i++)
#pragma unroll
                for (int j = 0; j < TN; j++)
                    acc[i][j] += a[i] * b[j];
        }
        __syncthreads();
    }

    // epilogue
#pragma unroll
    for (int i = 0; i < TM; i++) {
        int r = rowBase + ty*TM + i;
        if (r >= M) continue;
#pragma unroll
        for (int j = 0; j < TN; j++) {
            int c = colBase + tx*TN + j;
            if (c >= N) continue;
            float v = acc[i][j] * alpha;
            if (bias) v += bias[c];
            if (EPI == 1) {                         // exact GELU
                v = 0.5f * v * (1.0f + erff(v * 0.70710678118654752f));
            } else if (EPI == 2) {
                v += Res[(long long)r*ldRes + c];
            }
            C[(long long)r*ldC + c] = v;
        }
    }
}

// ---------------- LayerNorm: one block per row ------------------------------
__global__ void ln_kernel(const float* __restrict__ in,
                          const float* __restrict__ w,
                          const float* __restrict__ b,
                          float* __restrict__ out)
{
    const long long row = blockIdx.x;
    const int tid = threadIdx.x;   // 256
    const float* rp = in + row*CC;
    float v0 = rp[tid], v1 = rp[tid+256], v2 = rp[tid+512];
    float s = v0+v1+v2, ss = v0*v0 + v1*v1 + v2*v2;

    __shared__ float rs[256], rq[256];
    rs[tid] = s; rq[tid] = ss;
    __syncthreads();
    for (int off = 128; off > 0; off >>= 1) {
        if (tid < off) { rs[tid] += rs[tid+off]; rq[tid] += rq[tid+off]; }
        __syncthreads();
    }
    float mean = rs[0] * (1.0f/CC);
    float var  = rq[0] * (1.0f/CC) - mean*mean;
    float rstd = rsqrtf(var + EPS_);

    float* op = out + row*CC;
    op[tid]      = (v0 - mean)*rstd * w[tid]      + b[tid];
    op[tid+256]  = (v1 - mean)*rstd * w[tid+256]  + b[tid+256];
    op[tid+512]  = (v2 - mean)*rstd * w[tid+512]  + b[tid+512];
}

// ------- patch_attn extract + CLS-row factor + softmax (in place) ----------
// grid: (N rows, B*H), block 256.  Row length 577 = 2*256 + 65.
__global__ void softmax_factor_kernel(float* __restrict__ S,
                                      const float* __restrict__ attn_weight,
                                      float* __restrict__ patch_out)
{
    const int z = blockIdx.y;            // b*H + h
    const int n = blockIdx.x;            // query row
    const int tid = threadIdx.x;
    const int b = z / HH_;
    float* row = S + (long long)z*SMAT + (long long)n*NN_;

    float vals[3];
    float m = -INFINITY;
#pragma unroll
    for (int r = 0; r < 3; r++) {
        int j = tid + r*256;
        float v = -INFINITY;
        if (j < NN_) {
            v = row[j];
            if (n == 0 && j > 0) {
                // patch_attn: pre-factor, post-scale scores
                patch_out[((long long)z)*(NN_-1) + (j-1)] = v;
                v *= attn_weight[(long long)b*(NN_-1) + (j-1)] * ALPHA_ + (1.0f - ALPHA_);
            }
        }
        vals[r] = v;
        m = fmaxf(m, v);
    }

    __shared__ float red[256];
    red[tid] = m; __syncthreads();
    for (int off = 128; off > 0; off >>= 1) {
        if (tid < off) red[tid] = fmaxf(red[tid], red[tid+off]);
        __syncthreads();
    }
    m = red[0];
    __syncthreads();

    float s = 0.f;
#pragma unroll
    for (int r = 0; r < 3; r++) {
        int j = tid + r*256;
        if (j < NN_) { vals[r] = expf(vals[r] - m); s += vals[r]; }
    }
    red[tid] = s; __syncthreads();
    for (int off = 128; off > 0; off >>= 1) {
        if (tid < off) red[tid] += red[tid+off];
        __syncthreads();
    }
    float inv = 1.0f / red[0];
#pragma unroll
    for (int r = 0; r < 3; r++) {
        int j = tid + r*256;
        if (j < NN_) row[j] = vals[r] * inv;
    }
}

// ---------------------------------------------------------------------------
extern "C" void kernel_launch(void* const* d_in, const int* in_sizes, int n_in,
                              void* d_out, int out_size)
{
    const float* x      = (const float*)d_in[0];
    const float* attn_w = (const float*)d_in[1];
    const float* ln1_w  = (const float*)d_in[2];
    const float* ln1_b  = (const float*)d_in[3];
    const float* qkv_w  = (const float*)d_in[4];
    const float* qkv_b  = (const float*)d_in[5];
    const float* proj_w = (const float*)d_in[6];
    const float* proj_b = (const float*)d_in[7];
    const float* ln2_w  = (const float*)d_in[8];
    const float* ln2_b  = (const float*)d_in[9];
    const float* fc1_w  = (const float*)d_in[10];
    const float* fc1_b  = (const float*)d_in[11];
    const float* fc2_w  = (const float*)d_in[12];
    const float* fc2_b  = (const float*)d_in[13];

    float* out_x     = (float*)d_out;                      // [B,N,C]
    float* out_patch = out_x + (long long)ROWS*CC;         // [B,H,N-1]

    float* hln  = nullptr; cudaGetSymbolAddress((void**)&hln,  g_hln);
    float* qkv  = nullptr; cudaGetSymbolAddress((void**)&qkv,  g_qkv);
    float* sc   = nullptr; cudaGetSymbolAddress((void**)&sc,   g_scores);
    float* aout = nullptr; cudaGetSymbolAddress((void**)&aout, g_attnout);
    float* x1   = nullptr; cudaGetSymbolAddress((void**)&x1,   g_x1);
    float* h2   = nullptr; cudaGetSymbolAddress((void**)&h2,   g_h2ln);
    float* fc1o = nullptr; cudaGetSymbolAddress((void**)&fc1o, g_fc1);

    dim3 thr(16, 16);

    // 1) LN1
    ln_kernel<<<ROWS, 256>>>(x, ln1_w, ln1_b, hln);

    // 2) qkv = hln @ qkv_w^T + qkv_b      [18464, 2304]
    gemm_k<128,128,8,8,8,true,0><<<dim3((3*CC+127)/128, (ROWS+127)/128, 1), thr>>>(
        hln, qkv_w, qkv, ROWS, 3*CC, CC, CC, CC, 3*CC,
        1, 0,0, 0,0, 0,0, qkv_b, nullptr, 0, 1.0f);

    // 3) scores[z] = SCALE * Q_z @ K_z^T   (z = b*H + h), [577,577]
    gemm_k<128,128,8,8,8,true,0><<<dim3((NN_+127)/128, (NN_+127)/128, BB*HH_), thr>>>(
        qkv, qkv + CC, sc, NN_, NN_, DD, 3*CC, 3*CC, NN_,
        HH_, (long long)NN_*3*CC, DD,
             (long long)NN_*3*CC, DD,
             (long long)HH_*SMAT, SMAT,
        nullptr, nullptr, 0, SCALE_);

    // 4) patch_attn extract + CLS factor + softmax
    softmax_factor_kernel<<<dim3(NN_, BB*HH_), 256>>>(sc, attn_w, out_patch);

    // 5) attn_out[b,n, h*64+d] = P_z @ V_z     (NN GEMM: K=577, N=64)
    gemm_k<64,64,8,4,4,false,0><<<dim3(1, (NN_+63)/64, BB*HH_), thr>>>(
        sc, qkv + 2*CC, aout, NN_, DD, NN_, NN_, 3*CC, CC,
        HH_, (long long)HH_*SMAT, SMAT,
             (long long)NN_*3*CC, DD,
             (long long)NN_*CC,   DD,
        nullptr, nullptr, 0, 1.0f);

    // 6) x1 = x + aout @ proj_w^T + proj_b
    gemm_k<128,128,8,8,8,true,2><<<dim3((CC+127)/128, (ROWS+127)/128, 1), thr>>>(
        aout, proj_w, x1, ROWS, CC, CC, CC, CC, CC,
        1, 0,0, 0,0, 0,0, proj_b, x, CC, 1.0f);

    // 7) LN2
    ln_kernel<<<ROWS, 256>>>(x1, ln2_w, ln2_b, h2);

    // 8) fc1o = gelu(h2 @ fc1_w^T + fc1_b)   [18464, 3072]
    gemm_k<128,128,8,8,8,true,1><<<dim3((HID_+127)/128, (ROWS+127)/128, 1), thr>>>(
        h2, fc1_w, fc1o, ROWS, HID_, CC, CC, CC, HID_,
        1, 0,0, 0,0, 0,0, fc1_b, nullptr, 0, 1.0f);

    // 9) out_x = x1 + fc1o @ fc2_w^T + fc2_b
    gemm_k<128,128,8,8,8,true,2><<<dim3((CC+127)/128, (ROWS+127)/128, 1), thr>>>(
        fc1o, fc2_w, out_x, ROWS, CC, HID_, HID_, HID_, CC,
        1, 0,0, 0,0, 0,0, fc2_b, x1, CC, 1.0f);
}

// round 5
// speedup vs baseline: 2.8963x; 2.8963x over previous
#include <cuda_runtime.h>
#include <cuda_bf16.h>
#include <math.h>
#include <stdint.h>

// Problem constants
#define BB   32
#define NN_  577
#define CC   768
#define HH_  12
#define DD   64
#define HID_ 3072
#define ROWS (BB*NN_)                    // 18464
#define SLD  608                         // padded leading dim (mult of 32 for K-tiling)
#define SSTRIDE ((long long)NN_*SLD)     // per-(b,h) scores stride
#define ALPHA_ 0.1f
#define EPS_ 1e-6f
#define SCALE_ 0.125f                    // D^-0.5

// ---------------- scratch (static device arrays; zero-initialized) ---------
__device__ float g_hln [ (long long)ROWS*CC ];
__device__ float g_qkv [ (long long)ROWS*3*CC ];
__device__ float g_scores[ (long long)BB*HH_*SSTRIDE + 4096 ];
__device__ float g_vt  [ (long long)BB*HH_*DD*SLD + 4096 ];
__device__ float g_attnout[ (long long)ROWS*CC ];
__device__ float g_x1  [ (long long)ROWS*CC ];
__device__ float g_h2ln[ (long long)ROWS*CC ];
__device__ float g_fc1 [ (long long)ROWS*HID_ ];

// =================== mma.sync helpers ======================================
#define MMA16816(d, a0,a1,a2,a3, b0,b1) \
    asm volatile("mma.sync.aligned.m16n8k16.row.col.f32.bf16.bf16.f32 " \
        "{%0,%1,%2,%3}, {%4,%5,%6,%7}, {%8,%9}, {%0,%1,%2,%3};" \
        : "+f"((d)[0]), "+f"((d)[1]), "+f"((d)[2]), "+f"((d)[3]) \
        : "r"(a0), "r"(a1), "r"(a2), "r"(a3), "r"(b0), "r"(b1))

__device__ __forceinline__ uint32_t pack_bf2(float x, float y) {
    __nv_bfloat16 hx = __float2bfloat16_rn(x);
    __nv_bfloat16 hy = __float2bfloat16_rn(y);
    return ((uint32_t)__bfloat16_as_ushort(hy) << 16) | __bfloat16_as_ushort(hx);
}

// =================== HMMA GEMM =============================================
// C[M,N] = epi( alpha * A[M,K] @ B^T + bias ),  A [M,K] ldA, B [N,K] ldB (fp32).
// bf16x3 split (hi*hi + hi*lo + lo*hi) for fp32-level accuracy.
// BM=128, BK=32 per tile, 256 threads = 8 warps (4 m-groups x 2 n-groups).
// Requires K % 32 == 0.
// EPI: 0 none, 1 exact GELU, 2 residual add.
template<int BN, int EPI>
__global__ void __launch_bounds__(256)
gemm_mma(const float* __restrict__ A, const float* __restrict__ Bm,
         float* __restrict__ C,
         int M, int N, int K,
         int ldA, int ldB, int ldC,
         int HB,
         long long sAo, long long sAi,
         long long sBo, long long sBi,
         long long sCo, long long sCi,
         const float* __restrict__ bias,
         const float* __restrict__ Res, int ldRes,
         float alpha)
{
    constexpr int BM  = 128;
    constexpr int AU  = 20;                 // u32 stride per row (16 data + 4 pad)
    constexpr int NT  = BN / 16;            // n8 tiles per warp
    constexpr int ACH = 4;                  // A float4 chunks per thread
    constexpr int BCH = BN * 8 / 256;       // B float4 chunks per thread
    constexpr int ATILE = BM * AU;          // 2560 u32
    constexpr int BTILE = BN * AU;

    const int tid  = threadIdx.x;
    const int wid  = tid >> 5;
    const int lane = tid & 31;
    const int gq   = lane >> 2;             // group id 0..7
    const int tq   = lane & 3;              // thread-in-group 0..3
    const int warp_m = wid & 3;
    const int warp_n = wid >> 2;

    const int z = blockIdx.z, zo = z / HB, zi = z % HB;
    A  += zo * sAo + zi * sAi;
    Bm += zo * sBo + zi * sBi;
    C  += zo * sCo + zi * sCi;
    const int rowBase = blockIdx.y * BM;
    const int colBase = blockIdx.x * BN;

    extern __shared__ uint32_t sm[];
    uint32_t* Ah = sm;
    uint32_t* Al = sm + ATILE;
    uint32_t* Bh = sm + 2*ATILE;
    uint32_t* Bl = sm + 2*ATILE + BTILE;

    float acc[2][NT][4];
#pragma unroll
    for (int i = 0; i < 2; i++)
#pragma unroll
        for (int j = 0; j < NT; j++)
#pragma unroll
            for (int q = 0; q < 4; q++) acc[i][j][q] = 0.f;

    float4 pa[ACH], pb[BCH];

    auto ld_tiles = [&](int k0) {
#pragma unroll
        for (int i = 0; i < ACH; i++) {
            int cid = tid + i*256;
            int row = cid >> 3, kc = (cid & 7) * 4;
            int gr = rowBase + row;
            pa[i] = (gr < M) ? *reinterpret_cast<const float4*>(A + (long long)gr*ldA + k0 + kc)
                             : make_float4(0.f,0.f,0.f,0.f);
        }
#pragma unroll
        for (int i = 0; i < BCH; i++) {
            int cid = tid + i*256;
            int row = cid >> 3, kc = (cid & 7) * 4;
            int gn = colBase + row;
            pb[i] = (gn < N) ? *reinterpret_cast<const float4*>(Bm + (long long)gn*ldB + k0 + kc)
                             : make_float4(0.f,0.f,0.f,0.f);
        }
    };

    auto st_tiles = [&]() {
#pragma unroll
        for (int i = 0; i < ACH; i++) {
            int cid = tid + i*256;
            int row = cid >> 3, kc = cid & 7;
            int idx = row*AU + kc*2;
            float4 v = pa[i];
            uint32_t h0 = pack_bf2(v.x, v.y), h1 = pack_bf2(v.z, v.w);
            float rx = v.x - __bfloat162float(__ushort_as_bfloat16((unsigned short)(h0 & 0xffff)));
            float ry = v.y - __bfloat162float(__ushort_as_bfloat16((unsigned short)(h0 >> 16)));
            float rz = v.z - __bfloat162float(__ushort_as_bfloat16((unsigned short)(h1 & 0xffff)));
            float rw = v.w - __bfloat162float(__ushort_as_bfloat16((unsigned short)(h1 >> 16)));
            Ah[idx] = h0; Ah[idx+1] = h1;
            Al[idx] = pack_bf2(rx, ry); Al[idx+1] = pack_bf2(rz, rw);
        }
#pragma unroll
        for (int i = 0; i < BCH; i++) {
            int cid = tid + i*256;
            int row = cid >> 3, kc = cid & 7;
            int idx = row*AU + kc*2;
            float4 v = pb[i];
            uint32_t h0 = pack_bf2(v.x, v.y), h1 = pack_bf2(v.z, v.w);
            float rx = v.x - __bfloat162float(__ushort_as_bfloat16((unsigned short)(h0 & 0xffff)));
            float ry = v.y - __bfloat162float(__ushort_as_bfloat16((unsigned short)(h0 >> 16)));
            float rz = v.z - __bfloat162float(__ushort_as_bfloat16((unsigned short)(h1 & 0xffff)));
            float rw = v.w - __bfloat162float(__ushort_as_bfloat16((unsigned short)(h1 >> 16)));
            Bh[idx] = h0; Bh[idx+1] = h1;
            Bl[idx] = pack_bf2(rx, ry); Bl[idx+1] = pack_bf2(rz, rw);
        }
    };

    const int nst = K / 32;
    ld_tiles(0);
    for (int s = 0; s < nst; s++) {
        st_tiles();
        __syncthreads();
        if (s + 1 < nst) ld_tiles((s + 1) * 32);

        // compute on current tile
#pragma unroll
        for (int ks = 0; ks < 2; ks++) {
            const int kb = ks * 8;
            uint32_t ah[2][4], al[2][4];
#pragma unroll
            for (int i = 0; i < 2; i++) {
                int r0 = warp_m*32 + i*16 + gq;
                ah[i][0] = Ah[(r0  )*AU + kb + tq];
                ah[i][1] = Ah[(r0+8)*AU + kb + tq];
                ah[i][2] = Ah[(r0  )*AU + kb + tq + 4];
                ah[i][3] = Ah[(r0+8)*AU + kb + tq + 4];
                al[i][0] = Al[(r0  )*AU + kb + tq];
                al[i][1] = Al[(r0+8)*AU + kb + tq];
                al[i][2] = Al[(r0  )*AU + kb + tq + 4];
                al[i][3] = Al[(r0+8)*AU + kb + tq + 4];
            }
#pragma unroll
            for (int j = 0; j < NT; j++) {
                int n = warp_n*(BN/2) + j*8 + gq;
                uint32_t bh0 = Bh[n*AU + kb + tq];
                uint32_t bh1 = Bh[n*AU + kb + tq + 4];
                uint32_t bl0 = Bl[n*AU + kb + tq];
                uint32_t bl1 = Bl[n*AU + kb + tq + 4];
#pragma unroll
                for (int i = 0; i < 2; i++) {
                    MMA16816(acc[i][j], ah[i][0], ah[i][1], ah[i][2], ah[i][3], bh0, bh1);
                    MMA16816(acc[i][j], ah[i][0], ah[i][1], ah[i][2], ah[i][3], bl0, bl1);
                    MMA16816(acc[i][j], al[i][0], al[i][1], al[i][2], al[i][3], bh0, bh1);
                }
            }
        }
        __syncthreads();
    }

    // epilogue
#pragma unroll
    for (int i = 0; i < 2; i++) {
        int r0 = rowBase + warp_m*32 + i*16 + gq;
#pragma unroll
        for (int j = 0; j < NT; j++) {
            int c0 = colBase + warp_n*(BN/2) + j*8 + tq*2;
#pragma unroll
            for (int half = 0; half < 2; half++) {
                int r = r0 + half*8;
                if (r >= M) continue;
#pragma unroll
                for (int q = 0; q < 2; q++) {
                    int c = c0 + q;
                    if (c >= N) continue;
                    float v = acc[i][j][half*2 + q] * alpha;
                    if (bias) v += bias[c];
                    if (EPI == 1) v = 0.5f * v * (1.0f + erff(v * 0.70710678118654752f));
                    else if (EPI == 2) v += Res[(long long)r*ldRes + c];
                    C[(long long)r*ldC + c] = v;
                }
            }
        }
    }
}

// ---------------- LayerNorm: one block per row ------------------------------
__global__ void ln_kernel(const float* __restrict__ in,
                          const float* __restrict__ w,
                          const float* __restrict__ b,
                          float* __restrict__ out)
{
    const long long row = blockIdx.x;
    const int tid = threadIdx.x;   // 256
    const float* rp = in + row * CC;
    float v0 = rp[tid], v1 = rp[tid+256], v2 = rp[tid+512];
    float s = v0+v1+v2, ss = v0*v0 + v1*v1 + v2*v2;

    const int wid = tid >> 5, lid = tid & 31;
    for (int o = 16; o; o >>= 1) { s += __shfl_xor_sync(0xffffffffu, s, o); ss += __shfl_xor_sync(0xffffffffu, ss, o); }
    __shared__ float rs[8], rq[8];
    if (lid == 0) { rs[wid] = s; rq[wid] = ss; }
    __syncthreads();
    float ts = 0.f, tq = 0.f;
#pragma unroll
    for (int i = 0; i < 8; i++) { ts += rs[i]; tq += rq[i]; }
    float mean = ts * (1.0f/CC);
    float var  = tq * (1.0f/CC) - mean*mean;
    float rstd = rsqrtf(var + EPS_);

    float* op = out + row * CC;
    op[tid]     = (v0 - mean)*rstd * w[tid]     + b[tid];
    op[tid+256] = (v1 - mean)*rstd * w[tid+256] + b[tid+256];
    op[tid+512] = (v2 - mean)*rstd * w[tid+512] + b[tid+512];
}

// ------- patch_attn extract + CLS-row factor + softmax (in place) ----------
__global__ void softmax_factor_kernel(float* __restrict__ S,
                                      const float* __restrict__ attn_weight,
                                      float* __restrict__ patch_out)
{
    const int z = blockIdx.y, n = blockIdx.x, tid = threadIdx.x;
    const int wid = tid >> 5, lid = tid & 31;
    const int b = z / HH_;
    float* row = S + (long long)z * SSTRIDE + (long long)n * SLD;

    float vals[3], m = -INFINITY;
#pragma unroll
    for (int r = 0; r < 3; r++) {
        int j = tid + r*256;
        float v = -INFINITY;
        if (j < NN_) {
            v = row[j];
            if (n == 0 && j > 0) {
                patch_out[(long long)z*(NN_-1) + (j-1)] = v;
                v *= attn_weight[(long long)b*(NN_-1) + (j-1)] * ALPHA_ + (1.0f - ALPHA_);
            }
        }
        vals[r] = v; m = fmaxf(m, v);
    }
    for (int o = 16; o; o >>= 1) m = fmaxf(m, __shfl_xor_sync(0xffffffffu, m, o));
    __shared__ float sm8[8], ssum[8];
    if (lid == 0) sm8[wid] = m;
    __syncthreads();
    m = sm8[0];
#pragma unroll
    for (int i = 1; i < 8; i++) m = fmaxf(m, sm8[i]);

    float s = 0.f;
#pragma unroll
    for (int r = 0; r < 3; r++) {
        int j = tid + r*256;
        if (j < NN_) { vals[r] = __expf(vals[r] - m); s += vals[r]; }
    }
    for (int o = 16; o; o >>= 1) s += __shfl_xor_sync(0xffffffffu, s, o);
    if (lid == 0) ssum[wid] = s;
    __syncthreads();
    float tot = 0.f;
#pragma unroll
    for (int i = 0; i < 8; i++) tot += ssum[i];
    float inv = 1.0f / tot;
#pragma unroll
    for (int r = 0; r < 3; r++) {
        int j = tid + r*256;
        if (j < NN_) row[j] = vals[r] * inv;
    }
}

// ---- V transpose: vt[z][d, m] = qkv[b*N+m, 2C + h*64 + d], ld SLD ----------
// Also zero-pads m in [NN_, SLD) so the AV GEMM can run K=SLD unguarded.
__global__ void vtrans_kernel(const float* __restrict__ qkv, float* __restrict__ vt)
{
    __shared__ float t[32][33];
    const int z = blockIdx.z, b = z / HH_, h = z % HH_;
    const int m0 = blockIdx.x * 32, d0 = blockIdx.y * 32;
    const int x = threadIdx.x, y = threadIdx.y;   // 32 x 8
    for (int yy = y; yy < 32; yy += 8) {
        int m = m0 + yy;
        float v = 0.f;
        if (m < NN_) v = qkv[((long long)(b*NN_ + m))*(3*CC) + 2*CC + h*DD + d0 + x];
        t[yy][x] = v;
    }
    __syncthreads();
    for (int yy = y; yy < 32; yy += 8) {
        int d = d0 + yy, m = m0 + x;
        if (m < SLD) vt[(long long)z*DD*SLD + (long long)d*SLD + m] = t[x][yy];
    }
}

// ---------------------------------------------------------------------------
extern "C" void kernel_launch(void* const* d_in, const int* in_sizes, int n_in,
                              void* d_out, int out_size)
{
    const float* x      = (const float*)d_in[0];
    const float* attn_w = (const float*)d_in[1];
    const float* ln1_w  = (const float*)d_in[2];
    const float* ln1_b  = (const float*)d_in[3];
    const float* qkv_w  = (const float*)d_in[4];
    const float* qkv_b  = (const float*)d_in[5];
    const float* proj_w = (const float*)d_in[6];
    const float* proj_b = (const float*)d_in[7];
    const float* ln2_w  = (const float*)d_in[8];
    const float* ln2_b  = (const float*)d_in[9];
    const float* fc1_w  = (const float*)d_in[10];
    const float* fc1_b  = (const float*)d_in[11];
    const float* fc2_w  = (const float*)d_in[12];
    const float* fc2_b  = (const float*)d_in[13];

    float* out_x     = (float*)d_out;
    float* out_patch = out_x + (long long)ROWS*CC;

    float* hln;  cudaGetSymbolAddress((void**)&hln,  g_hln);
    float* qkv;  cudaGetSymbolAddress((void**)&qkv,  g_qkv);
    float* sc;   cudaGetSymbolAddress((void**)&sc,   g_scores);
    float* vt;   cudaGetSymbolAddress((void**)&vt,   g_vt);
    float* aout; cudaGetSymbolAddress((void**)&aout, g_attnout);
    float* x1;   cudaGetSymbolAddress((void**)&x1,   g_x1);
    float* h2;   cudaGetSymbolAddress((void**)&h2,   g_h2ln);
    float* fc1o; cudaGetSymbolAddress((void**)&fc1o, g_fc1);

    const int SM128 = (2*128*20 + 2*128*20) * 4;   // 40960 B
    const int SM64  = (2*128*20 + 2*64*20) * 4;    // 30720 B

    // 1) LN1
    ln_kernel<<<ROWS, 256>>>(x, ln1_w, ln1_b, hln);

    // 2) qkv = hln @ qkv_w^T + qkv_b      [18464, 2304] K=768
    gemm_mma<128,0><<<dim3((3*CC)/128, (ROWS+127)/128, 1), 256, SM128>>>(
        hln, qkv_w, qkv, ROWS, 3*CC, CC, CC, CC, 3*CC,
        1, 0,0, 0,0, 0,0, qkv_b, nullptr, 0, 1.0f);

    // 3) scores[z] = SCALE * Q_z @ K_z^T   [577,577] K=64, ldC=SLD
    gemm_mma<128,0><<<dim3((NN_+127)/128, (NN_+127)/128, BB*HH_), 256, SM128>>>(
        qkv, qkv + CC, sc, NN_, NN_, DD, 3*CC, 3*CC, SLD,
        HH_, (long long)NN_*3*CC, DD,
             (long long)NN_*3*CC, DD,
             (long long)HH_*SSTRIDE, SSTRIDE,
        nullptr, nullptr, 0, SCALE_);

    // 4) patch_attn extract + CLS factor + softmax
    softmax_factor_kernel<<<dim3(NN_, BB*HH_), 256>>>(sc, attn_w, out_patch);

    // 5) V transpose -> vt[z][d, m] (zero-padded to SLD)
    vtrans_kernel<<<dim3(SLD/32, 2, BB*HH_), dim3(32, 8)>>>(qkv, vt);

    // 6) attn_out = P_z @ V_z   (A [577,SLD] ld SLD, B vt [64,SLD] ld SLD) K=SLD
    gemm_mma<64,0><<<dim3(1, (NN_+127)/128, BB*HH_), 256, SM64>>>(
        sc, vt, aout, NN_, DD, SLD, SLD, SLD, CC,
        HH_, (long long)HH_*SSTRIDE, SSTRIDE,
             (long long)HH_*DD*SLD,  (long long)DD*SLD,
             (long long)NN_*CC,      DD,
        nullptr, nullptr, 0, 1.0f);

    // 7) x1 = x + aout @ proj_w^T + proj_b   K=768
    gemm_mma<128,2><<<dim3(CC/128, (ROWS+127)/128, 1), 256, SM128>>>(
        aout, proj_w, x1, ROWS, CC, CC, CC, CC, CC,
        1, 0,0, 0,0, 0,0, proj_b, x, CC, 1.0f);

    // 8) LN2
    ln_kernel<<<ROWS, 256>>>(x1, ln2_w, ln2_b, h2);

    // 9) fc1o = gelu(h2 @ fc1_w^T + fc1_b)   [18464, 3072] K=768
    gemm_mma<128,1><<<dim3(HID_/128, (ROWS+127)/128, 1), 256, SM128>>>(
        h2, fc1_w, fc1o, ROWS, HID_, CC, CC, CC, HID_,
        1, 0,0, 0,0, 0,0, fc1_b, nullptr, 0, 1.0f);

    // 10) out_x = x1 + fc1o @ fc2_w^T + fc2_b   K=3072
    gemm_mma<128,2><<<dim3(CC/128, (ROWS+127)/128, 1), 256, SM128>>>(
        fc1o, fc2_w, out_x, ROWS, CC, HID_, HID_, HID_, CC,
        1, 0,0, 0,0, 0,0, fc2_b, x1, CC, 1.0f);
}

// round 6
// speedup vs baseline: 3.8122x; 1.3162x over previous
#include <cuda_runtime.h>
#include <cuda_bf16.h>
#include <math.h>
#include <stdint.h>

typedef unsigned short u16;

// Problem constants
#define BB   32
#define NN_  577
#define CC   768
#define HH_  12
#define DD   64
#define HID_ 3072
#define ROWS (BB*NN_)                    // 18464
#define SLD  608                         // padded ld (mult of 32)
#define SSTRIDE ((long long)NN_*SLD)
#define ALPHA_ 0.1f
#define EPS_ 1e-6f
#define SCALE_ 0.125f

// ---------------- scratch --------------------------------------------------
__device__ u16 g_hlnH[(long long)ROWS*CC],  g_hlnL[(long long)ROWS*CC];
__device__ u16 g_qkvwH[(long long)3*CC*CC], g_qkvwL[(long long)3*CC*CC];
__device__ u16 g_projwH[(long long)CC*CC],  g_projwL[(long long)CC*CC];
__device__ u16 g_fc1wH[(long long)HID_*CC], g_fc1wL[(long long)HID_*CC];
__device__ u16 g_fc2wH[(long long)CC*HID_], g_fc2wL[(long long)CC*HID_];
__device__ u16 g_qkvH[(long long)ROWS*3*CC], g_qkvL[(long long)ROWS*3*CC];
__device__ float g_scores[(long long)BB*HH_*SSTRIDE + 4096];
__device__ u16 g_PH[(long long)BB*HH_*SSTRIDE + 4096], g_PL[(long long)BB*HH_*SSTRIDE + 4096];
__device__ u16 g_vtH[(long long)BB*HH_*DD*SLD + 4096], g_vtL[(long long)BB*HH_*DD*SLD + 4096];
__device__ u16 g_aoutH[(long long)ROWS*CC], g_aoutL[(long long)ROWS*CC];
__device__ float g_x1[(long long)ROWS*CC];
__device__ u16 g_h2H[(long long)ROWS*CC],  g_h2L[(long long)ROWS*CC];
__device__ u16 g_fc1H[(long long)ROWS*HID_], g_fc1L[(long long)ROWS*HID_];

// =================== asm helpers ===========================================
#define MMA16816(d, a0,a1,a2,a3, b0,b1) \
    asm volatile("mma.sync.aligned.m16n8k16.row.col.f32.bf16.bf16.f32 " \
        "{%0,%1,%2,%3}, {%4,%5,%6,%7}, {%8,%9}, {%0,%1,%2,%3};" \
        : "+f"((d)[0]), "+f"((d)[1]), "+f"((d)[2]), "+f"((d)[3]) \
        : "r"(a0), "r"(a1), "r"(a2), "r"(a3), "r"(b0), "r"(b1))

#define LDSM4(r, ad) \
    asm volatile("ldmatrix.sync.aligned.m8n8.x4.shared.b16 {%0,%1,%2,%3}, [%4];" \
        : "=r"((r)[0]), "=r"((r)[1]), "=r"((r)[2]), "=r"((r)[3]) : "r"(ad))

__device__ __forceinline__ void cpa16(uint32_t dst, const void* src, int sz) {
    asm volatile("cp.async.cg.shared.global [%0], [%1], 16, %2;" :: "r"(dst), "l"(src), "r"(sz) : "memory");
}
#define CP_COMMIT() asm volatile("cp.async.commit_group;" ::: "memory")
#define CP_WAIT1()  asm volatile("cp.async.wait_group 1;" ::: "memory")
#define CP_WAIT0()  asm volatile("cp.async.wait_group 0;" ::: "memory")

__device__ __forceinline__ uint32_t smem_u32(const void* p) {
    uint32_t a;
    asm("{ .reg .u64 t; cvta.to.shared.u64 t, %1; cvt.u32.u64 %0, t; }" : "=r"(a) : "l"(p));
    return a;
}
__device__ __forceinline__ uint32_t pack_bf2(float x, float y) {
    __nv_bfloat16 hx = __float2bfloat16_rn(x);
    __nv_bfloat16 hy = __float2bfloat16_rn(y);
    return ((uint32_t)__bfloat16_as_ushort(hy) << 16) | __bfloat16_as_ushort(hx);
}
__device__ __forceinline__ void split_bf(float v, u16& h, u16& l) {
    __nv_bfloat16 hb = __float2bfloat16_rn(v);
    h = __bfloat16_as_ushort(hb);
    l = __bfloat16_as_ushort(__float2bfloat16_rn(v - __bfloat162float(hb)));
}

// =================== bf16-pair HMMA GEMM ===================================
// C = epi(alpha * A @ B^T + bias); A [M,K] (AH,AL), B [N,K] (BH,BL), bf16.
// BM=128, BK=32, 256 threads (4x2 warps; warp tile 32 x BN/2).
// cp.async double-buffered; ldmatrix fragments; 3 MMA passes (hh, hl, lh).
// K % 32 == 0 required. Row base addrs must be 16B aligned (ld % 8 == 0).
// EPI: 0 none, 1 exact GELU, 2 +Res.  OUTB: 0 fp32 C, 1 bf16 pair CH/CL.
template<int BN, int EPI, int OUTB>
__global__ void __launch_bounds__(256, 2)
gemm_bf(const u16* __restrict__ AH, const u16* __restrict__ AL,
        const u16* __restrict__ BH, const u16* __restrict__ BL,
        float* __restrict__ C, u16* __restrict__ CH, u16* __restrict__ CL,
        int M, int N, int K, int ldA, int ldB, int ldC,
        int HB,
        long long sAo, long long sAi, long long sBo, long long sBi,
        long long sCo, long long sCi,
        const float* __restrict__ bias,
        const float* __restrict__ Res, int ldRes, float alpha)
{
    constexpr int ABYTES = 128 * 80;            // 128 rows x (64B data + 16B pad)
    constexpr int BBYTES = BN * 80;
    constexpr int STAGE  = 2*ABYTES + 2*BBYTES;
    constexpr int NT     = BN / 16;             // n8 tiles per warp
    constexpr int BCH    = BN / 64;             // B cp.async chunks per thread

    const int tid = threadIdx.x, lane = tid & 31, wid = tid >> 5;
    const int gq = lane >> 2, tq = lane & 3;
    const int warp_m = wid & 3, warp_n = wid >> 2;

    const int z = blockIdx.z, zo = z / HB, zi = z % HB;
    AH += zo*sAo + zi*sAi;  AL += zo*sAo + zi*sAi;
    BH += zo*sBo + zi*sBi;  BL += zo*sBo + zi*sBi;
    if (OUTB) { CH += zo*sCo + zi*sCi; CL += zo*sCo + zi*sCi; }
    else      { C  += zo*sCo + zi*sCi; }
    const int rowBase = blockIdx.y * 128;
    const int colBase = blockIdx.x * BN;

    extern __shared__ char smraw[];
    const uint32_t smb = smem_u32(smraw);

    float acc[2][NT][4];
#pragma unroll
    for (int i = 0; i < 2; i++)
#pragma unroll
        for (int j = 0; j < NT; j++)
#pragma unroll
            for (int q = 0; q < 4; q++) acc[i][j][q] = 0.f;

    const int nst = K / 32;

    auto load_stage = [&](int s) {
        const int k0 = s * 32;
        const uint32_t base = smb + (s & 1) * STAGE;
#pragma unroll
        for (int i = 0; i < 2; i++) {
            int cid = tid + i*256;
            int row = cid >> 2, q = cid & 3;
            int gr = rowBase + row;
            int sz = (gr < M) ? 16 : 0;
            long long go = (long long)(gr < M ? gr : 0) * ldA + k0 + q*8;
            uint32_t so = row*80 + q*16;
            cpa16(base + so,          AH + go, sz);
            cpa16(base + ABYTES + so, AL + go, sz);
        }
#pragma unroll
        for (int i = 0; i < BCH; i++) {
            int cid = tid + i*256;
            int row = cid >> 2, q = cid & 3;
            int gn = colBase + row;
            int sz = (gn < N) ? 16 : 0;
            long long go = (long long)(gn < N ? gn : 0) * ldB + k0 + q*8;
            uint32_t so = row*80 + q*16;
            cpa16(base + 2*ABYTES + so,          BH + go, sz);
            cpa16(base + 2*ABYTES + BBYTES + so, BL + go, sz);
        }
    };

    // fragment smem offsets (per lane)
    const uint32_t lrow = lane & 15, lsel = lane >> 4;
    const uint32_t aOff = (warp_m*32 + lrow)*80 + lsel*16;
    const uint32_t bOff = (warp_n*(BN/2) + lrow)*80 + lsel*16;

    load_stage(0);
    CP_COMMIT();

    for (int s = 0; s < nst; s++) {
        if (s + 1 < nst) { load_stage(s + 1); CP_COMMIT(); CP_WAIT1(); }
        else             { CP_WAIT0(); }
        __syncthreads();

        const uint32_t st = smb + (s & 1) * STAGE;
#pragma unroll
        for (int ks = 0; ks < 2; ks++) {
            uint32_t ah[2][4], al[2][4];
#pragma unroll
            for (int i = 0; i < 2; i++) {
                LDSM4(ah[i], st + aOff + i*1280 + ks*32);
                LDSM4(al[i], st + ABYTES + aOff + i*1280 + ks*32);
            }
#pragma unroll
            for (int j2 = 0; j2 < NT/2; j2++) {
                uint32_t bh[4], bl[4];
                LDSM4(bh, st + 2*ABYTES + bOff + j2*1280 + ks*32);
                LDSM4(bl, st + 2*ABYTES + BBYTES + bOff + j2*1280 + ks*32);
#pragma unroll
                for (int i = 0; i < 2; i++) {
                    MMA16816(acc[i][2*j2],   ah[i][0],ah[i][1],ah[i][2],ah[i][3], bh[0], bh[2]);
                    MMA16816(acc[i][2*j2+1], ah[i][0],ah[i][1],ah[i][2],ah[i][3], bh[1], bh[3]);
                    MMA16816(acc[i][2*j2],   ah[i][0],ah[i][1],ah[i][2],ah[i][3], bl[0], bl[2]);
                    MMA16816(acc[i][2*j2+1], ah[i][0],ah[i][1],ah[i][2],ah[i][3], bl[1], bl[3]);
                    MMA16816(acc[i][2*j2],   al[i][0],al[i][1],al[i][2],al[i][3], bh[0], bh[2]);
                    MMA16816(acc[i][2*j2+1], al[i][0],al[i][1],al[i][2],al[i][3], bh[1], bh[3]);
                }
            }
        }
        __syncthreads();
    }

    // epilogue
#pragma unroll
    for (int i = 0; i < 2; i++) {
#pragma unroll
        for (int half = 0; half < 2; half++) {
            const int r = rowBase + warp_m*32 + i*16 + gq + half*8;
            if (r >= M) continue;
#pragma unroll
            for (int j = 0; j < NT; j++) {
                const int c0 = colBase + warp_n*(BN/2) + j*8 + tq*2;
                float v0 = acc[i][j][half*2 + 0] * alpha;
                float v1 = acc[i][j][half*2 + 1] * alpha;
                if (bias) { v0 += bias[c0]; v1 += (c0+1 < N) ? bias[c0+1] : 0.f; }
                if (EPI == 1) {
                    v0 = 0.5f*v0*(1.0f + erff(v0*0.70710678118654752f));
                    v1 = 0.5f*v1*(1.0f + erff(v1*0.70710678118654752f));
                } else if (EPI == 2) {
                    v0 += Res[(long long)r*ldRes + c0];
                    if (c0+1 < N) v1 += Res[(long long)r*ldRes + c0 + 1];
                }
                if (OUTB) {
                    if (c0 + 1 < N) {
                        u16 h0,l0,h1,l1;
                        split_bf(v0, h0, l0); split_bf(v1, h1, l1);
                        *reinterpret_cast<uint32_t*>(CH + (long long)r*ldC + c0) = ((uint32_t)h1<<16)|h0;
                        *reinterpret_cast<uint32_t*>(CL + (long long)r*ldC + c0) = ((uint32_t)l1<<16)|l0;
                    } else if (c0 < N) {
                        u16 h0,l0; split_bf(v0, h0, l0);
                        CH[(long long)r*ldC + c0] = h0; CL[(long long)r*ldC + c0] = l0;
                    }
                } else {
                    if (c0 < N)     C[(long long)r*ldC + c0]     = v0;
                    if (c0+1 < N)   C[(long long)r*ldC + c0 + 1] = v1;
                }
            }
        }
    }
}

// ---------------- weight fp32 -> bf16 hi/lo --------------------------------
__global__ void conv_pair(const float* __restrict__ src, u16* __restrict__ hi,
                          u16* __restrict__ lo, long long n4)
{
    long long i = (long long)blockIdx.x * blockDim.x + threadIdx.x;
    if (i >= n4) return;
    float4 v = reinterpret_cast<const float4*>(src)[i];
    u16 h0,l0,h1,l1,h2,l2,h3,l3;
    split_bf(v.x,h0,l0); split_bf(v.y,h1,l1); split_bf(v.z,h2,l2); split_bf(v.w,h3,l3);
    uint2 hp = { ((uint32_t)h1<<16)|h0, ((uint32_t)h3<<16)|h2 };
    uint2 lp = { ((uint32_t)l1<<16)|l0, ((uint32_t)l3<<16)|l2 };
    reinterpret_cast<uint2*>(hi)[i] = hp;
    reinterpret_cast<uint2*>(lo)[i] = lp;
}

// ---------------- LayerNorm -> bf16 hi/lo ----------------------------------
__global__ void ln_kernel(const float* __restrict__ in,
                          const float* __restrict__ w, const float* __restrict__ b,
                          u16* __restrict__ outH, u16* __restrict__ outL)
{
    const long long row = blockIdx.x;
    const int tid = threadIdx.x;
    const float* rp = in + row * CC;
    float v0 = rp[tid], v1 = rp[tid+256], v2 = rp[tid+512];
    float s = v0+v1+v2, ss = v0*v0 + v1*v1 + v2*v2;
    const int wid = tid >> 5, lid = tid & 31;
    for (int o = 16; o; o >>= 1) { s += __shfl_xor_sync(~0u, s, o); ss += __shfl_xor_sync(~0u, ss, o); }
    __shared__ float rs[8], rq[8];
    if (lid == 0) { rs[wid] = s; rq[wid] = ss; }
    __syncthreads();
    float ts = 0.f, tq = 0.f;
#pragma unroll
    for (int i = 0; i < 8; i++) { ts += rs[i]; tq += rq[i]; }
    float mean = ts * (1.0f/CC);
    float rstd = rsqrtf(tq * (1.0f/CC) - mean*mean + EPS_);
#pragma unroll
    for (int k = 0; k < 3; k++) {
        int c = tid + k*256;
        float v = (k==0?v0:(k==1?v1:v2));
        float y = (v - mean)*rstd * w[c] + b[c];
        u16 h,l; split_bf(y,h,l);
        outH[row*CC + c] = h; outL[row*CC + c] = l;
    }
}

// ------- patch extract + CLS factor + softmax -> P bf16 hi/lo --------------
__global__ void softmax_factor_kernel(const float* __restrict__ S,
                                      u16* __restrict__ PH, u16* __restrict__ PL,
                                      const float* __restrict__ attn_weight,
                                      float* __restrict__ patch_out)
{
    const int z = blockIdx.y, n = blockIdx.x, tid = threadIdx.x;
    const int wid = tid >> 5, lid = tid & 31;
    const int b = z / HH_;
    const float* row = S + (long long)z*SSTRIDE + (long long)n*SLD;
    u16* ph = PH + (long long)z*SSTRIDE + (long long)n*SLD;
    u16* pl = PL + (long long)z*SSTRIDE + (long long)n*SLD;

    float vals[3], m = -INFINITY;
#pragma unroll
    for (int r = 0; r < 3; r++) {
        int j = tid + r*256;
        float v = -INFINITY;
        if (j < NN_) {
            v = row[j];
            if (n == 0 && j > 0) {
                patch_out[(long long)z*(NN_-1) + (j-1)] = v;
                v *= attn_weight[(long long)b*(NN_-1) + (j-1)] * ALPHA_ + (1.0f - ALPHA_);
            }
        }
        vals[r] = v; m = fmaxf(m, v);
    }
    for (int o = 16; o; o >>= 1) m = fmaxf(m, __shfl_xor_sync(~0u, m, o));
    __shared__ float sm8[8], ssum[8];
    if (lid == 0) sm8[wid] = m;
    __syncthreads();
    m = sm8[0];
#pragma unroll
    for (int i = 1; i < 8; i++) m = fmaxf(m, sm8[i]);

    float s = 0.f;
#pragma unroll
    for (int r = 0; r < 3; r++) {
        int j = tid + r*256;
        if (j < NN_) { vals[r] = __expf(vals[r] - m); s += vals[r]; }
    }
    for (int o = 16; o; o >>= 1) s += __shfl_xor_sync(~0u, s, o);
    if (lid == 0) ssum[wid] = s;
    __syncthreads();
    float tot = 0.f;
#pragma unroll
    for (int i = 0; i < 8; i++) tot += ssum[i];
    float inv = 1.0f / tot;
#pragma unroll
    for (int r = 0; r < 3; r++) {
        int j = tid + r*256;
        if (j < NN_) {
            float p = vals[r] * inv;
            u16 h,l; split_bf(p,h,l);
            ph[j] = h; pl[j] = l;
        }
    }
    if (tid < SLD - NN_) { ph[NN_ + tid] = 0; pl[NN_ + tid] = 0; }  // zero pad
}

// ---- V transpose (bf16): vt[z][d, m] = qkv[b*N+m][2C + h*64 + d] ----------
__global__ void vtrans_kernel(const u16* __restrict__ qH, const u16* __restrict__ qL,
                              u16* __restrict__ vtH, u16* __restrict__ vtL)
{
    __shared__ u16 th[32][33], tl[32][33];
    const int z = blockIdx.z, b = z / HH_, h = z % HH_;
    const int m0 = blockIdx.x * 32, d0 = blockIdx.y * 32;
    const int x = threadIdx.x, y = threadIdx.y;   // 32 x 8
    for (int yy = y; yy < 32; yy += 8) {
        int m = m0 + yy;
        u16 vh = 0, vl = 0;
        if (m < NN_) {
            long long o = (long long)(b*NN_ + m)*(3*CC) + 2*CC + h*DD + d0 + x;
            vh = qH[o]; vl = qL[o];
        }
        th[yy][x] = vh; tl[yy][x] = vl;
    }
    __syncthreads();
    for (int yy = y; yy < 32; yy += 8) {
        int d = d0 + yy, m = m0 + x;
        long long o = (long long)z*DD*SLD + (long long)d*SLD + m;
        vtH[o] = th[x][yy]; vtL[o] = tl[x][yy];
    }
}

// ---------------------------------------------------------------------------
extern "C" void kernel_launch(void* const* d_in, const int* in_sizes, int n_in,
                              void* d_out, int out_size)
{
    const float* x      = (const float*)d_in[0];
    const float* attn_w = (const float*)d_in[1];
    const float* ln1_w  = (const float*)d_in[2];
    const float* ln1_b  = (const float*)d_in[3];
    const float* qkv_w  = (const float*)d_in[4];
    const float* qkv_b  = (const float*)d_in[5];
    const float* proj_w = (const float*)d_in[6];
    const float* proj_b = (const float*)d_in[7];
    const float* ln2_w  = (const float*)d_in[8];
    const float* ln2_b  = (const float*)d_in[9];
    const float* fc1_w  = (const float*)d_in[10];
    const float* fc1_b  = (const float*)d_in[11];
    const float* fc2_w  = (const float*)d_in[12];
    const float* fc2_b  = (const float*)d_in[13];

    float* out_x     = (float*)d_out;
    float* out_patch = out_x + (long long)ROWS*CC;

    u16 *hlnH,*hlnL,*qkvwH,*qkvwL,*projwH,*projwL,*fc1wH,*fc1wL,*fc2wH,*fc2wL;
    u16 *qkvH,*qkvL,*PH,*PL,*vtH,*vtL,*aoutH,*aoutL,*h2H,*h2L,*fc1H,*fc1L;
    float *sc,*x1;
    cudaGetSymbolAddress((void**)&hlnH, g_hlnH);   cudaGetSymbolAddress((void**)&hlnL, g_hlnL);
    cudaGetSymbolAddress((void**)&qkvwH, g_qkvwH); cudaGetSymbolAddress((void**)&qkvwL, g_qkvwL);
    cudaGetSymbolAddress((void**)&projwH, g_projwH); cudaGetSymbolAddress((void**)&projwL, g_projwL);
    cudaGetSymbolAddress((void**)&fc1wH, g_fc1wH); cudaGetSymbolAddress((void**)&fc1wL, g_fc1wL);
    cudaGetSymbolAddress((void**)&fc2wH, g_fc2wH); cudaGetSymbolAddress((void**)&fc2wL, g_fc2wL);
    cudaGetSymbolAddress((void**)&qkvH, g_qkvH);   cudaGetSymbolAddress((void**)&qkvL, g_qkvL);
    cudaGetSymbolAddress((void**)&sc, g_scores);
    cudaGetSymbolAddress((void**)&PH, g_PH);       cudaGetSymbolAddress((void**)&PL, g_PL);
    cudaGetSymbolAddress((void**)&vtH, g_vtH);     cudaGetSymbolAddress((void**)&vtL, g_vtL);
    cudaGetSymbolAddress((void**)&aoutH, g_aoutH); cudaGetSymbolAddress((void**)&aoutL, g_aoutL);
    cudaGetSymbolAddress((void**)&x1, g_x1);
    cudaGetSymbolAddress((void**)&h2H, g_h2H);     cudaGetSymbolAddress((void**)&h2L, g_h2L);
    cudaGetSymbolAddress((void**)&fc1H, g_fc1H);   cudaGetSymbolAddress((void**)&fc1L, g_fc1L);

    const int SMEM128 = 2 * (2*128*80 + 2*128*80);   // 81920
    const int SMEM64  = 2 * (2*128*80 + 2*64*80);    // 61440
    cudaFuncSetAttribute(gemm_bf<128,0,1>, cudaFuncAttributeMaxDynamicSharedMemorySize, SMEM128);
    cudaFuncSetAttribute(gemm_bf<128,0,0>, cudaFuncAttributeMaxDynamicSharedMemorySize, SMEM128);
    cudaFuncSetAttribute(gemm_bf<128,1,1>, cudaFuncAttributeMaxDynamicSharedMemorySize, SMEM128);
    cudaFuncSetAttribute(gemm_bf<128,2,0>, cudaFuncAttributeMaxDynamicSharedMemorySize, SMEM128);
    cudaFuncSetAttribute(gemm_bf<64,0,1>,  cudaFuncAttributeMaxDynamicSharedMemorySize, SMEM64);

    // 0) weight conversions
    conv_pair<<<(int)(((long long)3*CC*CC/4 + 255)/256), 256>>>(qkv_w,  qkvwH,  qkvwL,  (long long)3*CC*CC/4);
    conv_pair<<<(int)(((long long)CC*CC/4   + 255)/256), 256>>>(proj_w, projwH, projwL, (long long)CC*CC/4);
    conv_pair<<<(int)(((long long)HID_*CC/4 + 255)/256), 256>>>(fc1_w,  fc1wH,  fc1wL,  (long long)HID_*CC/4);
    conv_pair<<<(int)(((long long)CC*HID_/4 + 255)/256), 256>>>(fc2_w,  fc2wH,  fc2wL,  (long long)CC*HID_/4);

    // 1) LN1 -> bf16 pair
    ln_kernel<<<ROWS, 256>>>(x, ln1_w, ln1_b, hlnH, hlnL);

    // 2) qkv = hln @ qkv_w^T + qkv_b  -> bf16 pair [ROWS, 2304]
    gemm_bf<128,0,1><<<dim3(3*CC/128, (ROWS+127)/128, 1), 256, SMEM128>>>(
        hlnH, hlnL, qkvwH, qkvwL, nullptr, qkvH, qkvL,
        ROWS, 3*CC, CC, CC, CC, 3*CC,
        1, 0,0, 0,0, 0,0, qkv_b, nullptr, 0, 1.0f);

    // 3) scores = SCALE * Q @ K^T  (fp32, ldC=SLD)
    gemm_bf<128,0,0><<<dim3((NN_+127)/128, (NN_+127)/128, BB*HH_), 256, SMEM128>>>(
        qkvH, qkvL, qkvH + CC, qkvL + CC, sc, nullptr, nullptr,
        NN_, NN_, DD, 3*CC, 3*CC, SLD,
        HH_, (long long)NN_*3*CC, DD, (long long)NN_*3*CC, DD,
             (long long)HH_*SSTRIDE, SSTRIDE,
        nullptr, nullptr, 0, SCALE_);

    // 4) softmax (+patch, +CLS factor) -> P bf16 pair
    softmax_factor_kernel<<<dim3(NN_, BB*HH_), 256>>>(sc, PH, PL, attn_w, out_patch);

    // 5) V transpose -> vt bf16 pair [z][64, SLD]
    vtrans_kernel<<<dim3(SLD/32, 2, BB*HH_), dim3(32, 8)>>>(qkvH, qkvL, vtH, vtL);

    // 6) attn_out = P @ V  -> aout bf16 pair (K=SLD)
    gemm_bf<64,0,1><<<dim3(1, (NN_+127)/128, BB*HH_), 256, SMEM64>>>(
        PH, PL, vtH, vtL, nullptr, aoutH, aoutL,
        NN_, DD, SLD, SLD, SLD, CC,
        HH_, (long long)HH_*SSTRIDE, SSTRIDE,
             (long long)HH_*DD*SLD,  (long long)DD*SLD,
             (long long)NN_*CC,      DD,
        nullptr, nullptr, 0, 1.0f);

    // 7) x1 = x + aout @ proj_w^T + proj_b  (fp32)
    gemm_bf<128,2,0><<<dim3(CC/128, (ROWS+127)/128, 1), 256, SMEM128>>>(
        aoutH, aoutL, projwH, projwL, x1, nullptr, nullptr,
        ROWS, CC, CC, CC, CC, CC,
        1, 0,0, 0,0, 0,0, proj_b, x, CC, 1.0f);

    // 8) LN2 -> bf16 pair
    ln_kernel<<<ROWS, 256>>>(x1, ln2_w, ln2_b, h2H, h2L);

    // 9) fc1 = gelu(h2 @ fc1_w^T + fc1_b) -> bf16 pair [ROWS, 3072]
    gemm_bf<128,1,1><<<dim3(HID_/128, (ROWS+127)/128, 1), 256, SMEM128>>>(
        h2H, h2L, fc1wH, fc1wL, nullptr, fc1H, fc1L,
        ROWS, HID_, CC, CC, CC, HID_,
        1, 0,0, 0,0, 0,0, fc1_b, nullptr, 0, 1.0f);

    // 10) out = x1 + fc1 @ fc2_w^T + fc2_b  (fp32, K=3072)
    gemm_bf<128,2,0><<<dim3(CC/128, (ROWS+127)/128, 1), 256, SMEM128>>>(
        fc1H, fc1L, fc2wH, fc2wL, out_x, nullptr, nullptr,
        ROWS, CC, HID_, HID_, HID_, CC,
        1, 0,0, 0,0, 0,0, fc2_b, x1, CC, 1.0f);
}

// round 7
// speedup vs baseline: 4.4846x; 1.1764x over previous
#include <cuda_runtime.h>
#include <cuda_bf16.h>
#include <math.h>
#include <stdint.h>

typedef unsigned short u16;

// Problem constants
#define BB   32
#define NN_  577
#define CC   768
#define HH_  12
#define DD   64
#define HID_ 3072
#define ROWS (BB*NN_)                    // 18464
#define SLD  608                         // padded key ld for vt
#define ALPHA_ 0.1f
#define EPS_ 1e-6f
#define SCALE_ 0.125f

// ---------------- scratch --------------------------------------------------
__device__ u16 g_hlnH[(long long)ROWS*CC],  g_hlnL[(long long)ROWS*CC];
__device__ u16 g_qkvwH[(long long)3*CC*CC], g_qkvwL[(long long)3*CC*CC];
__device__ u16 g_projwH[(long long)CC*CC],  g_projwL[(long long)CC*CC];
__device__ u16 g_fc1wH[(long long)HID_*CC], g_fc1wL[(long long)HID_*CC];
__device__ u16 g_fc2wH[(long long)CC*HID_], g_fc2wL[(long long)CC*HID_];
__device__ u16 g_qkvH[(long long)ROWS*3*CC], g_qkvL[(long long)ROWS*3*CC];
__device__ u16 g_vtH[(long long)BB*HH_*DD*SLD + 8192], g_vtL[(long long)BB*HH_*DD*SLD + 8192];
__device__ u16 g_aoutH[(long long)ROWS*CC], g_aoutL[(long long)ROWS*CC];
__device__ float g_x1[(long long)ROWS*CC];
__device__ u16 g_h2H[(long long)ROWS*CC],  g_h2L[(long long)ROWS*CC];
__device__ u16 g_fc1H[(long long)ROWS*HID_], g_fc1L[(long long)ROWS*HID_];

// =================== asm helpers ===========================================
#define MMA16816(d, a0,a1,a2,a3, b0,b1) \
    asm volatile("mma.sync.aligned.m16n8k16.row.col.f32.bf16.bf16.f32 " \
        "{%0,%1,%2,%3}, {%4,%5,%6,%7}, {%8,%9}, {%0,%1,%2,%3};" \
        : "+f"((d)[0]), "+f"((d)[1]), "+f"((d)[2]), "+f"((d)[3]) \
        : "r"(a0), "r"(a1), "r"(a2), "r"(a3), "r"(b0), "r"(b1))

#define LDSM4(r, ad) \
    asm volatile("ldmatrix.sync.aligned.m8n8.x4.shared.b16 {%0,%1,%2,%3}, [%4];" \
        : "=r"((r)[0]), "=r"((r)[1]), "=r"((r)[2]), "=r"((r)[3]) : "r"(ad))

__device__ __forceinline__ void cpa16(uint32_t dst, const void* src, int sz) {
    asm volatile("cp.async.cg.shared.global [%0], [%1], 16, %2;" :: "r"(dst), "l"(src), "r"(sz) : "memory");
}
#define CP_COMMIT() asm volatile("cp.async.commit_group;" ::: "memory")
#define CP_WAIT1()  asm volatile("cp.async.wait_group 1;" ::: "memory")
#define CP_WAIT0()  asm volatile("cp.async.wait_group 0;" ::: "memory")

__device__ __forceinline__ uint32_t smem_u32(const void* p) {
    uint32_t a;
    asm("{ .reg .u64 t; cvta.to.shared.u64 t, %1; cvt.u32.u64 %0, t; }" : "=r"(a) : "l"(p));
    return a;
}
__device__ __forceinline__ uint32_t pack_bf2(float x, float y) {
    __nv_bfloat16 hx = __float2bfloat16_rn(x);
    __nv_bfloat16 hy = __float2bfloat16_rn(y);
    return ((uint32_t)__bfloat16_as_ushort(hy) << 16) | __bfloat16_as_ushort(hx);
}
__device__ __forceinline__ void split_bf(float v, u16& h, u16& l) {
    __nv_bfloat16 hb = __float2bfloat16_rn(v);
    h = __bfloat16_as_ushort(hb);
    l = __bfloat16_as_ushort(__float2bfloat16_rn(v - __bfloat162float(hb)));
}
__device__ __forceinline__ float bf_hi(float v) {
    return __bfloat162float(__float2bfloat16_rn(v));
}

// =================== bf16-pair HMMA GEMM (unchanged from R6) ===============
template<int BN, int EPI, int OUTB>
__global__ void __launch_bounds__(256, 2)
gemm_bf(const u16* __restrict__ AH, const u16* __restrict__ AL,
        const u16* __restrict__ BH, const u16* __restrict__ BL,
        float* __restrict__ C, u16* __restrict__ CH, u16* __restrict__ CL,
        int M, int N, int K, int ldA, int ldB, int ldC,
        const float* __restrict__ bias,
        const float* __restrict__ Res, int ldRes, float alpha)
{
    constexpr int ABYTES = 128 * 80;
    constexpr int BBYTES = BN * 80;
    constexpr int STAGE  = 2*ABYTES + 2*BBYTES;
    constexpr int NT     = BN / 16;
    constexpr int BCH    = BN / 64;

    const int tid = threadIdx.x, lane = tid & 31, wid = tid >> 5;
    const int gq = lane >> 2, tq = lane & 3;
    const int warp_m = wid & 3, warp_n = wid >> 2;

    const int rowBase = blockIdx.y * 128;
    const int colBase = blockIdx.x * BN;

    extern __shared__ char smraw[];
    const uint32_t smb = smem_u32(smraw);

    float acc[2][NT][4];
#pragma unroll
    for (int i = 0; i < 2; i++)
#pragma unroll
        for (int j = 0; j < NT; j++)
#pragma unroll
            for (int q = 0; q < 4; q++) acc[i][j][q] = 0.f;

    const int nst = K / 32;

    auto load_stage = [&](int s) {
        const int k0 = s * 32;
        const uint32_t base = smb + (s & 1) * STAGE;
#pragma unroll
        for (int i = 0; i < 2; i++) {
            int cid = tid + i*256;
            int row = cid >> 2, q = cid & 3;
            int gr = rowBase + row;
            int sz = (gr < M) ? 16 : 0;
            long long go = (long long)(gr < M ? gr : 0) * ldA + k0 + q*8;
            uint32_t so = row*80 + q*16;
            cpa16(base + so,          AH + go, sz);
            cpa16(base + ABYTES + so, AL + go, sz);
        }
#pragma unroll
        for (int i = 0; i < BCH; i++) {
            int cid = tid + i*256;
            int row = cid >> 2, q = cid & 3;
            int gn = colBase + row;
            int sz = (gn < N) ? 16 : 0;
            long long go = (long long)(gn < N ? gn : 0) * ldB + k0 + q*8;
            uint32_t so = row*80 + q*16;
            cpa16(base + 2*ABYTES + so,          BH + go, sz);
            cpa16(base + 2*ABYTES + BBYTES + so, BL + go, sz);
        }
    };

    const uint32_t lrow = lane & 15, lsel = lane >> 4;
    const uint32_t aOff = (warp_m*32 + lrow)*80 + lsel*16;
    const uint32_t bOff = (warp_n*(BN/2) + lrow)*80 + lsel*16;

    load_stage(0);
    CP_COMMIT();

    for (int s = 0; s < nst; s++) {
        if (s + 1 < nst) { load_stage(s + 1); CP_COMMIT(); CP_WAIT1(); }
        else             { CP_WAIT0(); }
        __syncthreads();

        const uint32_t st = smb + (s & 1) * STAGE;
#pragma unroll
        for (int ks = 0; ks < 2; ks++) {
            uint32_t ah[2][4], al[2][4];
#pragma unroll
            for (int i = 0; i < 2; i++) {
                LDSM4(ah[i], st + aOff + i*1280 + ks*32);
                LDSM4(al[i], st + ABYTES + aOff + i*1280 + ks*32);
            }
#pragma unroll
            for (int j2 = 0; j2 < NT/2; j2++) {
                uint32_t bh[4], bl[4];
                LDSM4(bh, st + 2*ABYTES + bOff + j2*1280 + ks*32);
                LDSM4(bl, st + 2*ABYTES + BBYTES + bOff + j2*1280 + ks*32);
#pragma unroll
                for (int i = 0; i < 2; i++) {
                    MMA16816(acc[i][2*j2],   ah[i][0],ah[i][1],ah[i][2],ah[i][3], bh[0], bh[2]);
                    MMA16816(acc[i][2*j2+1], ah[i][0],ah[i][1],ah[i][2],ah[i][3], bh[1], bh[3]);
                    MMA16816(acc[i][2*j2],   ah[i][0],ah[i][1],ah[i][2],ah[i][3], bl[0], bl[2]);
                    MMA16816(acc[i][2*j2+1], ah[i][0],ah[i][1],ah[i][2],ah[i][3], bl[1], bl[3]);
                    MMA16816(acc[i][2*j2],   al[i][0],al[i][1],al[i][2],al[i][3], bh[0], bh[2]);
                    MMA16816(acc[i][2*j2+1], al[i][0],al[i][1],al[i][2],al[i][3], bh[1], bh[3]);
                }
            }
        }
        __syncthreads();
    }

#pragma unroll
    for (int i = 0; i < 2; i++) {
#pragma unroll
        for (int half = 0; half < 2; half++) {
            const int r = rowBase + warp_m*32 + i*16 + gq + half*8;
            if (r >= M) continue;
#pragma unroll
            for (int j = 0; j < NT; j++) {
                const int c0 = colBase + warp_n*(BN/2) + j*8 + tq*2;
                float v0 = acc[i][j][half*2 + 0] * alpha;
                float v1 = acc[i][j][half*2 + 1] * alpha;
                if (bias) { v0 += bias[c0]; v1 += (c0+1 < N) ? bias[c0+1] : 0.f; }
                if (EPI == 1) {
                    v0 = 0.5f*v0*(1.0f + erff(v0*0.70710678118654752f));
                    v1 = 0.5f*v1*(1.0f + erff(v1*0.70710678118654752f));
                } else if (EPI == 2) {
                    v0 += Res[(long long)r*ldRes + c0];
                    if (c0+1 < N) v1 += Res[(long long)r*ldRes + c0 + 1];
                }
                if (OUTB) {
                    if (c0 + 1 < N) {
                        u16 h0,l0,h1,l1;
                        split_bf(v0, h0, l0); split_bf(v1, h1, l1);
                        *reinterpret_cast<uint32_t*>(CH + (long long)r*ldC + c0) = ((uint32_t)h1<<16)|h0;
                        *reinterpret_cast<uint32_t*>(CL + (long long)r*ldC + c0) = ((uint32_t)l1<<16)|l0;
                    } else if (c0 < N) {
                        u16 h0,l0; split_bf(v0, h0, l0);
                        CH[(long long)r*ldC + c0] = h0; CL[(long long)r*ldC + c0] = l0;
                    }
                } else {
                    if (c0 < N)     C[(long long)r*ldC + c0]     = v0;
                    if (c0+1 < N)   C[(long long)r*ldC + c0 + 1] = v1;
                }
            }
        }
    }
}

// =================== fused flash attention =================================
// grid (5, B*H), 256 thr, 8 warps, each warp owns 16 q-rows.
// S = scale*Q@K^T (3-pass bf16 pair), CLS factor + patch_attn inline,
// online softmax, P repacked in regs, O += P@V (3-pass, V d-major from vt).
#define QSTR 144
#define VSTR 272
#define QHALF 18432            // 128*144
#define KBASE (2*QHALF)        // 36864
#define KSTG  (2*QHALF)        // per-stage K (hi+lo)
#define VBASE (KBASE + 2*KSTG) // 110592
#define VHALF 17408            // 64*272
#define VSTG  (2*VHALF)
#define FLASH_SMEM (VBASE + 2*VSTG)   // 180224

__global__ void __launch_bounds__(256, 1)
flash_attn(const u16* __restrict__ qkvH, const u16* __restrict__ qkvL,
           const u16* __restrict__ vtH, const u16* __restrict__ vtL,
           const float* __restrict__ attn_w,
           u16* __restrict__ aoutH, u16* __restrict__ aoutL,
           float* __restrict__ patch_out)
{
    const int z = blockIdx.y, qt = blockIdx.x;
    const int b = z / HH_, h = z % HH_;
    const int tid = threadIdx.x, lane = tid & 31, wid = tid >> 5;
    const int gq = lane >> 2, tq = lane & 3;

    extern __shared__ char smraw[];
    const uint32_t smb = smem_u32(smraw);

    // ---- load Q tile (once) ----
    {
#pragma unroll
        for (int i = 0; i < 4; i++) {
            int cid = tid + i*256;
            int row = cid >> 3, ch = cid & 7;
            int gr = qt*128 + row;
            int sz = (gr < NN_) ? 16 : 0;
            long long go = (long long)(b*NN_ + (gr < NN_ ? gr : 0))*(3*CC) + h*DD + ch*8;
            cpa16(smb + row*QSTR + ch*16,         qkvH + go, sz);
            cpa16(smb + QHALF + row*QSTR + ch*16, qkvL + go, sz);
        }
    }
    auto load_kv = [&](int t) {
        const uint32_t kb = smb + KBASE + (t & 1)*KSTG;
        const uint32_t vb = smb + VBASE + (t & 1)*VSTG;
#pragma unroll
        for (int i = 0; i < 4; i++) {
            int cid = tid + i*256;
            int row = cid >> 3, ch = cid & 7;
            int gk = t*128 + row;
            int sz = (gk < NN_) ? 16 : 0;
            long long go = (long long)(b*NN_ + (gk < NN_ ? gk : 0))*(3*CC) + CC + h*DD + ch*8;
            cpa16(kb + row*QSTR + ch*16,         qkvH + go, sz);
            cpa16(kb + QHALF + row*QSTR + ch*16, qkvL + go, sz);
        }
#pragma unroll
        for (int i = 0; i < 4; i++) {
            int cid = tid + i*256;
            int d = cid >> 4, ch = cid & 15;
            long long go = ((long long)z*DD + d)*SLD + t*128 + ch*8;
            cpa16(vb + d*VSTR + ch*16,         vtH + go, 16);
            cpa16(vb + VHALF + d*VSTR + ch*16, vtL + go, 16);
        }
    };

    float o[8][4];
#pragma unroll
    for (int j = 0; j < 8; j++)
#pragma unroll
        for (int q = 0; q < 4; q++) o[j][q] = 0.f;
    float m0 = -INFINITY, m1 = -INFINITY, l0 = 0.f, l1 = 0.f;

    const uint32_t lrow = lane & 15, lsel = lane >> 4;
    const uint32_t qOff = (wid*16 + lrow)*QSTR + lsel*16;
    const bool clsrow = (qt == 0) && (wid == 0) && (gq == 0);

    load_kv(0);
    CP_COMMIT();

    for (int t = 0; t < 5; t++) {
        if (t < 4) { load_kv(t + 1); CP_COMMIT(); CP_WAIT1(); }
        else       { CP_WAIT0(); }
        __syncthreads();

        const uint32_t kb = smb + KBASE + (t & 1)*KSTG;
        const uint32_t vb = smb + VBASE + (t & 1)*VSTG;

        // ---- S = Q @ K^T ----
        float s[16][4];
#pragma unroll
        for (int j = 0; j < 16; j++)
#pragma unroll
            for (int q = 0; q < 4; q++) s[j][q] = 0.f;

#pragma unroll
        for (int kg = 0; kg < 4; kg++) {
            uint32_t qh[4], ql[4];
            LDSM4(qh, smb + qOff + kg*32);
            LDSM4(ql, smb + QHALF + qOff + kg*32);
#pragma unroll
            for (int jj = 0; jj < 8; jj++) {
                uint32_t kh[4], kl[4];
                uint32_t ko = kb + (jj*16 + lrow)*QSTR + lsel*16 + kg*32;
                LDSM4(kh, ko);
                LDSM4(kl, ko + QHALF);
                MMA16816(s[2*jj],   qh[0],qh[1],qh[2],qh[3], kh[0], kh[2]);
                MMA16816(s[2*jj+1], qh[0],qh[1],qh[2],qh[3], kh[1], kh[3]);
                MMA16816(s[2*jj],   qh[0],qh[1],qh[2],qh[3], kl[0], kl[2]);
                MMA16816(s[2*jj+1], qh[0],qh[1],qh[2],qh[3], kl[1], kl[3]);
                MMA16816(s[2*jj],   ql[0],ql[1],ql[2],ql[3], kh[0], kh[2]);
                MMA16816(s[2*jj+1], ql[0],ql[1],ql[2],ql[3], kh[1], kh[3]);
            }
        }

        // ---- scale + CLS factor + patch + mask ----
#pragma unroll
        for (int jj = 0; jj < 16; jj++) {
#pragma unroll
            for (int qi = 0; qi < 4; qi++) {
                float v = s[jj][qi] * SCALE_;
                int key = t*128 + jj*8 + tq*2 + (qi & 1);
                if (clsrow && qi < 2) {
                    if (key >= 1 && key < NN_) {
                        patch_out[(long long)z*(NN_-1) + key - 1] = v;
                        v *= attn_w[(long long)b*(NN_-1) + key - 1] * ALPHA_ + (1.0f - ALPHA_);
                    }
                }
                if (key >= NN_) v = -1e30f;
                s[jj][qi] = v;
            }
        }

        // ---- online softmax ----
        float mx0 = -1e30f, mx1 = -1e30f;
#pragma unroll
        for (int jj = 0; jj < 16; jj++) {
            mx0 = fmaxf(mx0, fmaxf(s[jj][0], s[jj][1]));
            mx1 = fmaxf(mx1, fmaxf(s[jj][2], s[jj][3]));
        }
        mx0 = fmaxf(mx0, __shfl_xor_sync(~0u, mx0, 1)); mx0 = fmaxf(mx0, __shfl_xor_sync(~0u, mx0, 2));
        mx1 = fmaxf(mx1, __shfl_xor_sync(~0u, mx1, 1)); mx1 = fmaxf(mx1, __shfl_xor_sync(~0u, mx1, 2));
        float mn0 = fmaxf(m0, mx0), mn1 = fmaxf(m1, mx1);
        float f0 = __expf(m0 - mn0), f1 = __expf(m1 - mn1);
        m0 = mn0; m1 = mn1;
        float rs0 = 0.f, rs1 = 0.f;
#pragma unroll
        for (int jj = 0; jj < 16; jj++) {
            float p0 = __expf(s[jj][0] - m0), p1 = __expf(s[jj][1] - m0);
            float p2 = __expf(s[jj][2] - m1), p3 = __expf(s[jj][3] - m1);
            s[jj][0] = p0; s[jj][1] = p1; s[jj][2] = p2; s[jj][3] = p3;
            rs0 += p0 + p1; rs1 += p2 + p3;
        }
        rs0 += __shfl_xor_sync(~0u, rs0, 1); rs0 += __shfl_xor_sync(~0u, rs0, 2);
        rs1 += __shfl_xor_sync(~0u, rs1, 1); rs1 += __shfl_xor_sync(~0u, rs1, 2);
        l0 = l0*f0 + rs0; l1 = l1*f1 + rs1;
#pragma unroll
        for (int j = 0; j < 8; j++) {
            o[j][0] *= f0; o[j][1] *= f0; o[j][2] *= f1; o[j][3] *= f1;
        }

        // ---- O += P @ V ----
#pragma unroll
        for (int kg = 0; kg < 8; kg++) {
            uint32_t ah[4], al[4];
            {
                float v00 = s[2*kg][0],   v01 = s[2*kg][1],   v02 = s[2*kg][2],   v03 = s[2*kg][3];
                float v10 = s[2*kg+1][0], v11 = s[2*kg+1][1], v12 = s[2*kg+1][2], v13 = s[2*kg+1][3];
                ah[0] = pack_bf2(v00, v01); ah[1] = pack_bf2(v02, v03);
                ah[2] = pack_bf2(v10, v11); ah[3] = pack_bf2(v12, v13);
                al[0] = pack_bf2(v00 - bf_hi(v00), v01 - bf_hi(v01));
                al[1] = pack_bf2(v02 - bf_hi(v02), v03 - bf_hi(v03));
                al[2] = pack_bf2(v10 - bf_hi(v10), v11 - bf_hi(v11));
                al[3] = pack_bf2(v12 - bf_hi(v12), v13 - bf_hi(v13));
            }
#pragma unroll
            for (int jp = 0; jp < 4; jp++) {
                uint32_t vh[4], vl[4];
                uint32_t vo = vb + (jp*16 + lrow)*VSTR + lsel*16 + kg*32;
                LDSM4(vh, vo);
                LDSM4(vl, vo + VHALF);
                MMA16816(o[2*jp],   ah[0],ah[1],ah[2],ah[3], vh[0], vh[2]);
                MMA16816(o[2*jp+1], ah[0],ah[1],ah[2],ah[3], vh[1], vh[3]);
                MMA16816(o[2*jp],   ah[0],ah[1],ah[2],ah[3], vl[0], vl[2]);
                MMA16816(o[2*jp+1], ah[0],ah[1],ah[2],ah[3], vl[1], vl[3]);
                MMA16816(o[2*jp],   al[0],al[1],al[2],al[3], vh[0], vh[2]);
                MMA16816(o[2*jp+1], al[0],al[1],al[2],al[3], vh[1], vh[3]);
            }
        }
        __syncthreads();
    }

    // ---- epilogue: normalize and write aout pair ----
    const float inv0 = 1.0f / l0, inv1 = 1.0f / l1;
    const int q0 = qt*128 + wid*16 + gq, q1 = q0 + 8;
#pragma unroll
    for (int j = 0; j < 8; j++) {
        int d0 = j*8 + tq*2;
        if (q0 < NN_) {
            float v0 = o[j][0]*inv0, v1 = o[j][1]*inv0;
            u16 h0,lw0,h1,lw1; split_bf(v0,h0,lw0); split_bf(v1,h1,lw1);
            long long off = (long long)(b*NN_ + q0)*CC + h*DD + d0;
            *reinterpret_cast<uint32_t*>(aoutH + off) = ((uint32_t)h1<<16)|h0;
            *reinterpret_cast<uint32_t*>(aoutL + off) = ((uint32_t)lw1<<16)|lw0;
        }
        if (q1 < NN_) {
            float v0 = o[j][2]*inv1, v1 = o[j][3]*inv1;
            u16 h0,lw0,h1,lw1; split_bf(v0,h0,lw0); split_bf(v1,h1,lw1);
            long long off = (long long)(b*NN_ + q1)*CC + h*DD + d0;
            *reinterpret_cast<uint32_t*>(aoutH + off) = ((uint32_t)h1<<16)|h0;
            *reinterpret_cast<uint32_t*>(aoutL + off) = ((uint32_t)lw1<<16)|lw0;
        }
    }
}

// ---------------- weight fp32 -> bf16 hi/lo --------------------------------
__global__ void conv_pair(const float* __restrict__ src, u16* __restrict__ hi,
                          u16* __restrict__ lo, long long n4)
{
    long long i = (long long)blockIdx.x * blockDim.x + threadIdx.x;
    if (i >= n4) return;
    float4 v = reinterpret_cast<const float4*>(src)[i];
    u16 h0,l0,h1,l1,h2,l2,h3,l3;
    split_bf(v.x,h0,l0); split_bf(v.y,h1,l1); split_bf(v.z,h2,l2); split_bf(v.w,h3,l3);
    uint2 hp = { ((uint32_t)h1<<16)|h0, ((uint32_t)h3<<16)|h2 };
    uint2 lp = { ((uint32_t)l1<<16)|l0, ((uint32_t)l3<<16)|l2 };
    reinterpret_cast<uint2*>(hi)[i] = hp;
    reinterpret_cast<uint2*>(lo)[i] = lp;
}

// ---------------- LayerNorm -> bf16 hi/lo ----------------------------------
__global__ void ln_kernel(const float* __restrict__ in,
                          const float* __restrict__ w, const float* __restrict__ b,
                          u16* __restrict__ outH, u16* __restrict__ outL)
{
    const long long row = blockIdx.x;
    const int tid = threadIdx.x;
    const float* rp = in + row * CC;
    float v0 = rp[tid], v1 = rp[tid+256], v2 = rp[tid+512];
    float s = v0+v1+v2, ss = v0*v0 + v1*v1 + v2*v2;
    const int wid = tid >> 5, lid = tid & 31;
    for (int o = 16; o; o >>= 1) { s += __shfl_xor_sync(~0u, s, o); ss += __shfl_xor_sync(~0u, ss, o); }
    __shared__ float rs[8], rq[8];
    if (lid == 0) { rs[wid] = s; rq[wid] = ss; }
    __syncthreads();
    float ts = 0.f, tq = 0.f;
#pragma unroll
    for (int i = 0; i < 8; i++) { ts += rs[i]; tq += rq[i]; }
    float mean = ts * (1.0f/CC);
    float rstd = rsqrtf(tq * (1.0f/CC) - mean*mean + EPS_);
#pragma unroll
    for (int k = 0; k < 3; k++) {
        int c = tid + k*256;
        float v = (k==0?v0:(k==1?v1:v2));
        float y = (v - mean)*rstd * w[c] + b[c];
        u16 h,l; split_bf(y,h,l);
        outH[row*CC + c] = h; outL[row*CC + c] = l;
    }
}

// ---- V transpose (bf16): vt[z][d, m] = qkv[b*N+m][2C + h*64 + d] ----------
__global__ void vtrans_kernel(const u16* __restrict__ qH, const u16* __restrict__ qL,
                              u16* __restrict__ vtH, u16* __restrict__ vtL)
{
    __shared__ u16 th[32][33], tl[32][33];
    const int z = blockIdx.z, b = z / HH_, h = z % HH_;
    const int m0 = blockIdx.x * 32, d0 = blockIdx.y * 32;
    const int x = threadIdx.x, y = threadIdx.y;   // 32 x 8
    for (int yy = y; yy < 32; yy += 8) {
        int m = m0 + yy;
        u16 vh = 0, vl = 0;
        if (m < NN_) {
            long long o = (long long)(b*NN_ + m)*(3*CC) + 2*CC + h*DD + d0 + x;
            vh = qH[o]; vl = qL[o];
        }
        th[yy][x] = vh; tl[yy][x] = vl;
    }
    __syncthreads();
    for (int yy = y; yy < 32; yy += 8) {
        int d = d0 + yy, m = m0 + x;
        long long o = (long long)z*DD*SLD + (long long)d*SLD + m;
        vtH[o] = th[x][yy]; vtL[o] = tl[x][yy];
    }
}

// ---------------------------------------------------------------------------
extern "C" void kernel_launch(void* const* d_in, const int* in_sizes, int n_in,
                              void* d_out, int out_size)
{
    const float* x      = (const float*)d_in[0];
    const float* attn_w = (const float*)d_in[1];
    const float* ln1_w  = (const float*)d_in[2];
    const float* ln1_b  = (const float*)d_in[3];
    const float* qkv_w  = (const float*)d_in[4];
    const float* qkv_b  = (const float*)d_in[5];
    const float* proj_w = (const float*)d_in[6];
    const float* proj_b = (const float*)d_in[7];
    const float* ln2_w  = (const float*)d_in[8];
    const float* ln2_b  = (const float*)d_in[9];
    const float* fc1_w  = (const float*)d_in[10];
    const float* fc1_b  = (const float*)d_in[11];
    const float* fc2_w  = (const float*)d_in[12];
    const float* fc2_b  = (const float*)d_in[13];

    float* out_x     = (float*)d_out;
    float* out_patch = out_x + (long long)ROWS*CC;

    u16 *hlnH,*hlnL,*qkvwH,*qkvwL,*projwH,*projwL,*fc1wH,*fc1wL,*fc2wH,*fc2wL;
    u16 *qkvH,*qkvL,*vtH,*vtL,*aoutH,*aoutL,*h2H,*h2L,*fc1H,*fc1L;
    float *x1;
    cudaGetSymbolAddress((void**)&hlnH, g_hlnH);   cudaGetSymbolAddress((void**)&hlnL, g_hlnL);
    cudaGetSymbolAddress((void**)&qkvwH, g_qkvwH); cudaGetSymbolAddress((void**)&qkvwL, g_qkvwL);
    cudaGetSymbolAddress((void**)&projwH, g_projwH); cudaGetSymbolAddress((void**)&projwL, g_projwL);
    cudaGetSymbolAddress((void**)&fc1wH, g_fc1wH); cudaGetSymbolAddress((void**)&fc1wL, g_fc1wL);
    cudaGetSymbolAddress((void**)&fc2wH, g_fc2wH); cudaGetSymbolAddress((void**)&fc2wL, g_fc2wL);
    cudaGetSymbolAddress((void**)&qkvH, g_qkvH);   cudaGetSymbolAddress((void**)&qkvL, g_qkvL);
    cudaGetSymbolAddress((void**)&vtH, g_vtH);     cudaGetSymbolAddress((void**)&vtL, g_vtL);
    cudaGetSymbolAddress((void**)&aoutH, g_aoutH); cudaGetSymbolAddress((void**)&aoutL, g_aoutL);
    cudaGetSymbolAddress((void**)&x1, g_x1);
    cudaGetSymbolAddress((void**)&h2H, g_h2H);     cudaGetSymbolAddress((void**)&h2L, g_h2L);
    cudaGetSymbolAddress((void**)&fc1H, g_fc1H);   cudaGetSymbolAddress((void**)&fc1L, g_fc1L);

    const int SMEM128 = 2 * (2*128*80 + 2*128*80);   // 81920
    cudaFuncSetAttribute(gemm_bf<128,0,1>, cudaFuncAttributeMaxDynamicSharedMemorySize, SMEM128);
    cudaFuncSetAttribute(gemm_bf<128,1,1>, cudaFuncAttributeMaxDynamicSharedMemorySize, SMEM128);
    cudaFuncSetAttribute(gemm_bf<128,2,0>, cudaFuncAttributeMaxDynamicSharedMemorySize, SMEM128);
    cudaFuncSetAttribute(flash_attn, cudaFuncAttributeMaxDynamicSharedMemorySize, FLASH_SMEM);

    // 0) weight conversions
    conv_pair<<<(int)(((long long)3*CC*CC/4 + 255)/256), 256>>>(qkv_w,  qkvwH,  qkvwL,  (long long)3*CC*CC/4);
    conv_pair<<<(int)(((long long)CC*CC/4   + 255)/256), 256>>>(proj_w, projwH, projwL, (long long)CC*CC/4);
    conv_pair<<<(int)(((long long)HID_*CC/4 + 255)/256), 256>>>(fc1_w,  fc1wH,  fc1wL,  (long long)HID_*CC/4);
    conv_pair<<<(int)(((long long)CC*HID_/4 + 255)/256), 256>>>(fc2_w,  fc2wH,  fc2wL,  (long long)CC*HID_/4);

    // 1) LN1 -> bf16 pair
    ln_kernel<<<ROWS, 256>>>(x, ln1_w, ln1_b, hlnH, hlnL);

    // 2) qkv GEMM -> bf16 pair
    gemm_bf<128,0,1><<<dim3(3*CC/128, (ROWS+127)/128, 1), 256, SMEM128>>>(
        hlnH, hlnL, qkvwH, qkvwL, nullptr, qkvH, qkvL,
        ROWS, 3*CC, CC, CC, CC, 3*CC, qkv_b, nullptr, 0, 1.0f);

    // 3) V transpose (d-major, zero-padded keys to SLD)
    vtrans_kernel<<<dim3(SLD/32, 2, BB*HH_), dim3(32, 8)>>>(qkvH, qkvL, vtH, vtL);

    // 4) fused flash attention (scores + softmax + CLS factor + patch + AV)
    flash_attn<<<dim3(5, BB*HH_), 256, FLASH_SMEM>>>(
        qkvH, qkvL, vtH, vtL, attn_w, aoutH, aoutL, out_patch);

    // 5) x1 = x + aout @ proj_w^T + proj_b
    gemm_bf<128,2,0><<<dim3(CC/128, (ROWS+127)/128, 1), 256, SMEM128>>>(
        aoutH, aoutL, projwH, projwL, x1, nullptr, nullptr,
        ROWS, CC, CC, CC, CC, CC, proj_b, x, CC, 1.0f);

    // 6) LN2 -> bf16 pair
    ln_kernel<<<ROWS, 256>>>(x1, ln2_w, ln2_b, h2H, h2L);

    // 7) fc1 = gelu(...) -> bf16 pair
    gemm_bf<128,1,1><<<dim3(HID_/128, (ROWS+127)/128, 1), 256, SMEM128>>>(
        h2H, h2L, fc1wH, fc1wL, nullptr, fc1H, fc1L,
        ROWS, HID_, CC, CC, CC, HID_, fc1_b, nullptr, 0, 1.0f);

    // 8) out = x1 + fc1 @ fc2_w^T + fc2_b
    gemm_bf<128,2,0><<<dim3(CC/128, (ROWS+127)/128, 1), 256, SMEM128>>>(
        fc1H, fc1L, fc2wH, fc2wL, out_x, nullptr, nullptr,
        ROWS, CC, HID_, HID_, HID_, CC, fc2_b, x1, CC, 1.0f);
}